// round 2
// baseline (speedup 1.0000x reference)
#include <cuda_runtime.h>
#include <cuda_fp16.h>
#include <cstdint>

#define NROWS 16384
#define DIN   512
#define DOUT  256

#define KC 32
#define ASZ  (128 * 80)          // A tile: 128 rows x 32 halfs, padded to 80B rows
#define BSZ  (256 * 112)         // B tile: 256 rows x 32 halfs, padded to 112B rows
#define STAGE (ASZ + BSZ)        // 38912 B
#define SMEM_TOTAL (4 * STAGE)   // 155648 B

// scratch (16B-aligned via uint4)
__device__ uint4 g_WT4[DIN * DOUT / 8];     // W^T fp16 [n=256][k=512]
__device__ uint4 g_HT4[NROWS * DOUT / 8];   // H^T fp16 [n=256][k=16384]

// ---------------- helpers ----------------
__device__ __forceinline__ uint32_t smem_u32(const void* p) {
    uint32_t a;
    asm("{ .reg .u64 t; cvta.to.shared.u64 t, %1; cvt.u32.u64 %0, t; }"
        : "=r"(a) : "l"(p));
    return a;
}
__device__ __forceinline__ void cp_async16(uint32_t dst, const void* src) {
    asm volatile("cp.async.cg.shared.global [%0], [%1], 16;"
                 :: "r"(dst), "l"(src) : "memory");
}
__device__ __forceinline__ void cp_commit() {
    asm volatile("cp.async.commit_group;" ::: "memory");
}
__device__ __forceinline__ void cp_wait(int n) {
    if (n <= 0)      asm volatile("cp.async.wait_group 0;" ::: "memory");
    else if (n == 1) asm volatile("cp.async.wait_group 1;" ::: "memory");
    else             asm volatile("cp.async.wait_group 2;" ::: "memory");
}
__device__ __forceinline__ uint32_t lds32(uint32_t a) {
    uint32_t v;
    asm volatile("ld.shared.b32 %0, [%1];" : "=r"(v) : "r"(a));
    return v;
}
__device__ __forceinline__ void sts64(uint32_t a, uint32_t x, uint32_t y) {
    asm volatile("st.shared.v2.b32 [%0], {%1, %2};" :: "r"(a), "r"(x), "r"(y) : "memory");
}
__device__ __forceinline__ uint32_t pack2(float x, float y) {
    __half2 h = __floats2half2_rn(x, y);
    return *reinterpret_cast<uint32_t*>(&h);
}
__device__ __forceinline__ void mma16816(float* d, uint32_t a0, uint32_t a1,
                                         uint32_t a2, uint32_t a3,
                                         uint32_t b0, uint32_t b1) {
    asm volatile(
        "mma.sync.aligned.m16n8k16.row.col.f32.f16.f16.f32 "
        "{%0,%1,%2,%3}, {%4,%5,%6,%7}, {%8,%9}, {%0,%1,%2,%3};"
        : "+f"(d[0]), "+f"(d[1]), "+f"(d[2]), "+f"(d[3])
        : "r"(a0), "r"(a1), "r"(a2), "r"(a3), "r"(b0), "r"(b1));
}

// ---------------- W packing: W[k][n] f32 -> WT[n][k] f16 ----------------
__global__ void pack_w_kernel(const float* __restrict__ W) {
    int idx = blockIdx.x * blockDim.x + threadIdx.x;
    if (idx >= DIN * DOUT) return;
    int n = idx / DIN, k = idx % DIN;
    reinterpret_cast<__half*>(g_WT4)[idx] = __float2half_rn(W[(size_t)k * DOUT + n]);
}

// ---------------- warp-MMA GEMM ----------------
// C[M,256] = A[M,K](f32, converted in-flight) @ B[K,256] (B given transposed f16 [256][K])
// EPI 0: out f32 row-major [m][256]
// EPI 1: out f16 transposed [n][NROWS] with bias (writes H^T for GEMM2)
template<int EPI>
__global__ void __launch_bounds__(512, 1)
gemm_f16(const float* __restrict__ A, long long lda,
         const __half* __restrict__ B, long long ldb, int KT,
         float* __restrict__ outF, __half* __restrict__ outH,
         const float* __restrict__ bias)
{
    extern __shared__ char sm[];
    const uint32_t sb = smem_u32(sm);
    const int tid = threadIdx.x, lane = tid & 31, wid = tid >> 5;
    const int warp_m = wid & 3, warp_n = wid >> 2;
    const int g = lane >> 2, c = lane & 3;
    const float* aB = A + (size_t)blockIdx.x * 128 * (size_t)lda;

    float abuf[2][8];

    auto ldgA = [&](int kt, float* buf) {
        #pragma unroll
        for (int h = 0; h < 2; h++) {
            int q = tid + h * 512, row = q >> 3, seg = q & 7;
            const float4* p = reinterpret_cast<const float4*>(
                aB + (size_t)row * lda + kt * KC + seg * 4);
            float4 v = *p;
            buf[h * 4 + 0] = v.x; buf[h * 4 + 1] = v.y;
            buf[h * 4 + 2] = v.z; buf[h * 4 + 3] = v.w;
        }
    };
    auto stsA = [&](int kt, const float* buf) {
        uint32_t st = sb + (kt & 3) * STAGE;
        #pragma unroll
        for (int h = 0; h < 2; h++) {
            int q = tid + h * 512, row = q >> 3, seg = q & 7;
            sts64(st + row * 80 + seg * 8,
                  pack2(buf[h * 4 + 0], buf[h * 4 + 1]),
                  pack2(buf[h * 4 + 2], buf[h * 4 + 3]));
        }
    };
    auto cpB = [&](int kt) {
        uint32_t bt = sb + (kt & 3) * STAGE + ASZ;
        #pragma unroll
        for (int h = 0; h < 2; h++) {
            int q = tid + h * 512, row = q >> 2, seg = q & 3;
            cp_async16(bt + row * 112 + seg * 16,
                       B + (size_t)row * ldb + kt * KC + seg * 8);
        }
    };

    // prologue: stages 0..2 filled, chunk 3 staged in regs
    for (int kt = 0; kt < 3; kt++) {
        ldgA(kt, abuf[0]);
        stsA(kt, abuf[0]);
        cpB(kt);
        cp_commit();
    }
    ldgA(3, abuf[1]);

    float acc[2][8][4];
    #pragma unroll
    for (int mt = 0; mt < 2; mt++)
        #pragma unroll
        for (int nt = 0; nt < 8; nt++)
            #pragma unroll
            for (int e = 0; e < 4; e++) acc[mt][nt][e] = 0.f;

    for (int i = 0; i < KT; i++) {
        int w = KT - 1 - i;
        cp_wait(w > 2 ? 2 : w);
        __syncthreads();

        uint32_t as = sb + (i & 3) * STAGE;
        uint32_t bs = as + ASZ;
        #pragma unroll
        for (int k16 = 0; k16 < 2; k16++) {
            uint32_t a0[2], a1[2], a2[2], a3[2];
            #pragma unroll
            for (int mt = 0; mt < 2; mt++) {
                uint32_t base = as + (warp_m * 32 + mt * 16 + g) * 80 + k16 * 32 + c * 4;
                a0[mt] = lds32(base);
                a1[mt] = lds32(base + 8 * 80);
                a2[mt] = lds32(base + 16);
                a3[mt] = lds32(base + 8 * 80 + 16);
            }
            uint32_t b0[8], b1[8];
            #pragma unroll
            for (int nt = 0; nt < 8; nt++) {
                uint32_t bb = bs + (warp_n * 64 + nt * 8 + g) * 112 + k16 * 32 + c * 4;
                b0[nt] = lds32(bb);
                b1[nt] = lds32(bb + 16);
            }
            #pragma unroll
            for (int mt = 0; mt < 2; mt++)
                #pragma unroll
                for (int nt = 0; nt < 8; nt++)
                    mma16816(acc[mt][nt], a0[mt], a1[mt], a2[mt], a3[mt],
                             b0[nt], b1[nt]);
        }

        if (i + 3 < KT) {
            stsA(i + 3, abuf[(i + 3) & 1]);
            cpB(i + 3);
            cp_commit();
        }
        if (i + 4 < KT) ldgA(i + 4, abuf[(i + 4) & 1]);
    }

    // epilogue
    int m0 = blockIdx.x * 128 + warp_m * 32;
    #pragma unroll
    for (int mt = 0; mt < 2; mt++) {
        #pragma unroll
        for (int nt = 0; nt < 8; nt++) {
            int r = m0 + mt * 16 + g;
            int n = warp_n * 64 + nt * 8 + c * 2;
            if (EPI == 0) {
                float2 v0 = make_float2(acc[mt][nt][0], acc[mt][nt][1]);
                float2 v1 = make_float2(acc[mt][nt][2], acc[mt][nt][3]);
                *reinterpret_cast<float2*>(outF + (size_t)r * DOUT + n) = v0;
                *reinterpret_cast<float2*>(outF + (size_t)(r + 8) * DOUT + n) = v1;
            } else {
                float bn0 = bias[n], bn1 = bias[n + 1];
                outH[(size_t)n * NROWS + r]           = __float2half_rn(acc[mt][nt][0] + bn0);
                outH[(size_t)(n + 1) * NROWS + r]     = __float2half_rn(acc[mt][nt][1] + bn1);
                outH[(size_t)n * NROWS + r + 8]       = __float2half_rn(acc[mt][nt][2] + bn0);
                outH[(size_t)(n + 1) * NROWS + r + 8] = __float2half_rn(acc[mt][nt][3] + bn1);
            }
        }
    }
}

// ---------------- launch ----------------
extern "C" void kernel_launch(void* const* d_in, const int* in_sizes, int n_in,
                              void* d_out, int out_size) {
    const float* X = (const float*)d_in[0];
    const float* A = (const float*)d_in[1];
    const float* W = (const float*)d_in[2];
    const float* b = (const float*)d_in[3];
    float* out = (float*)d_out;

    static bool configured = false;
    cudaFuncSetAttribute(gemm_f16<0>, cudaFuncAttributeMaxDynamicSharedMemorySize, SMEM_TOTAL);
    cudaFuncSetAttribute(gemm_f16<1>, cudaFuncAttributeMaxDynamicSharedMemorySize, SMEM_TOTAL);
    (void)configured;

    void* wt = nullptr; void* ht = nullptr;
    cudaGetSymbolAddress(&wt, g_WT4);
    cudaGetSymbolAddress(&ht, g_HT4);

    pack_w_kernel<<<(DIN * DOUT + 255) / 256, 256>>>(W);
    // H^T = (X @ W + b)^T   (fp16, [256][16384])
    gemm_f16<1><<<128, 512, SMEM_TOTAL>>>(
        X, DIN, (const __half*)wt, DIN, DIN / KC, nullptr, (__half*)ht, b);
    // Out = A_hat @ H
    gemm_f16<0><<<128, 512, SMEM_TOTAL>>>(
        A, NROWS, (const __half*)ht, NROWS, NROWS / KC, out, nullptr, nullptr);
}

// round 3
// speedup vs baseline: 1.0150x; 1.0150x over previous
#include <cuda_runtime.h>
#include <cuda_fp16.h>
#include <cstdint>

#define NROWS 16384
#define DIN   512
#define DOUT  256

#define KC 32
#define ASZ  (128 * 80)          // A tile: 128 rows x 32 halfs, 80B padded rows
#define BSZ  (256 * 112)         // B tile: 256 rows x 32 halfs, 112B padded rows
#define STAGE (ASZ + BSZ)        // 38912 B
#define SMEM_TOTAL (4 * STAGE)   // 155648 B

// scratch
__device__ uint4 g_WT4[DIN * DOUT / 8];     // W^T fp16 [n=256][k=512]
__device__ uint4 g_HT4[NROWS * DOUT / 8];   // H^T fp16 [n=256][k=16384]

// ---------------- helpers ----------------
__device__ __forceinline__ uint32_t smem_u32(const void* p) {
    uint32_t a;
    asm("{ .reg .u64 t; cvta.to.shared.u64 t, %1; cvt.u32.u64 %0, t; }"
        : "=r"(a) : "l"(p));
    return a;
}
__device__ __forceinline__ void cp_async16(uint32_t dst, const void* src) {
    asm volatile("cp.async.cg.shared.global [%0], [%1], 16;"
                 :: "r"(dst), "l"(src) : "memory");
}
__device__ __forceinline__ void cp_commit() {
    asm volatile("cp.async.commit_group;" ::: "memory");
}
__device__ __forceinline__ void cp_wait(int n) {
    if (n <= 0)      asm volatile("cp.async.wait_group 0;" ::: "memory");
    else if (n == 1) asm volatile("cp.async.wait_group 1;" ::: "memory");
    else             asm volatile("cp.async.wait_group 2;" ::: "memory");
}
__device__ __forceinline__ void sts64(uint32_t a, uint32_t x, uint32_t y) {
    asm volatile("st.shared.v2.b32 [%0], {%1, %2};" :: "r"(a), "r"(x), "r"(y) : "memory");
}
__device__ __forceinline__ uint32_t pack2(float x, float y) {
    __half2 h = __floats2half2_rn(x, y);
    return *reinterpret_cast<uint32_t*>(&h);
}
__device__ __forceinline__ void ldsm4(uint32_t* r, uint32_t addr) {
    asm volatile("ldmatrix.sync.aligned.m8n8.x4.shared.b16 {%0,%1,%2,%3}, [%4];"
                 : "=r"(r[0]), "=r"(r[1]), "=r"(r[2]), "=r"(r[3]) : "r"(addr));
}
__device__ __forceinline__ void mma16816(float* d, const uint32_t* a,
                                         uint32_t b0, uint32_t b1) {
    asm volatile(
        "mma.sync.aligned.m16n8k16.row.col.f32.f16.f16.f32 "
        "{%0,%1,%2,%3}, {%4,%5,%6,%7}, {%8,%9}, {%0,%1,%2,%3};"
        : "+f"(d[0]), "+f"(d[1]), "+f"(d[2]), "+f"(d[3])
        : "r"(a[0]), "r"(a[1]), "r"(a[2]), "r"(a[3]), "r"(b0), "r"(b1));
}

// ---------------- W packing: W[k][n] f32 -> WT[n][k] f16 ----------------
__global__ void pack_w_kernel(const float* __restrict__ W) {
    int idx = blockIdx.x * blockDim.x + threadIdx.x;
    if (idx >= DIN * DOUT) return;
    int n = idx / DIN, k = idx % DIN;
    reinterpret_cast<__half*>(g_WT4)[idx] = __float2half_rn(W[(size_t)k * DOUT + n]);
}

// ---------------- warp-MMA GEMM ----------------
// C[128,256] per CTA = A[*,K](f32, cvt in-flight) @ B[K,256] (B stored [256][K] f16)
// 8 warps, warp tile 64x64 (warp_m = wid&1, warp_n = wid>>1)
template<int EPI>
__global__ void __launch_bounds__(256, 1)
gemm_f16(const float* __restrict__ A, long long lda,
         const __half* __restrict__ B, long long ldb, int KT,
         float* __restrict__ outF, __half* __restrict__ outH,
         const float* __restrict__ bias)
{
    extern __shared__ char sm[];
    const uint32_t sb = smem_u32(sm);
    const int tid = threadIdx.x, lane = tid & 31, wid = tid >> 5;
    const int warp_m = wid & 1, warp_n = wid >> 1;
    const int g = lane >> 2, c = lane & 3;
    const float* aB = A + (size_t)blockIdx.x * 128 * (size_t)lda;

    float abuf[2][16];

    auto ldgA = [&](int kt, float* buf) {
        #pragma unroll
        for (int h = 0; h < 4; h++) {
            int q = tid + h * 256, row = q >> 3, seg = q & 7;
            float4 v = *reinterpret_cast<const float4*>(
                aB + (size_t)row * lda + kt * KC + seg * 4);
            buf[h * 4 + 0] = v.x; buf[h * 4 + 1] = v.y;
            buf[h * 4 + 2] = v.z; buf[h * 4 + 3] = v.w;
        }
    };
    auto stsA = [&](int kt, const float* buf) {
        uint32_t st = sb + (kt & 3) * STAGE;
        #pragma unroll
        for (int h = 0; h < 4; h++) {
            int q = tid + h * 256, row = q >> 3, seg = q & 7;
            sts64(st + row * 80 + seg * 8,
                  pack2(buf[h * 4 + 0], buf[h * 4 + 1]),
                  pack2(buf[h * 4 + 2], buf[h * 4 + 3]));
        }
    };
    auto cpB = [&](int kt) {
        uint32_t bt = sb + (kt & 3) * STAGE + ASZ;
        #pragma unroll
        for (int h = 0; h < 4; h++) {
            int q = tid + h * 256, row = q >> 2, seg = q & 3;
            cp_async16(bt + row * 112 + seg * 16,
                       B + (size_t)row * ldb + kt * KC + seg * 8);
        }
    };

    for (int kt = 0; kt < 3; kt++) {
        ldgA(kt, abuf[kt & 1]);
        stsA(kt, abuf[kt & 1]);
        cpB(kt);
        cp_commit();
    }
    ldgA(3, abuf[1]);

    float acc[4][8][4];
    #pragma unroll
    for (int mt = 0; mt < 4; mt++)
        #pragma unroll
        for (int nt = 0; nt < 8; nt++)
            #pragma unroll
            for (int e = 0; e < 4; e++) acc[mt][nt][e] = 0.f;

    // ldmatrix source addresses (per-lane, stage-relative)
    // A: lanes 0-7 -> rows m+0..7 @k+0 | 8-15 -> m+8..15 @k+0 | 16-23 -> m+0..7 @k+16B | 24-31 -> m+8..15 @k+16B
    const uint32_t a_lm_off = (uint32_t)((warp_m * 64 + (lane & 15)) * 80 + (lane >> 4) * 16);
    // B: lanes 0-7 -> n+0..7 @k+0 | 8-15 -> n+0..7 @k+16B | 16-23 -> n+8..15 @k+0 | 24-31 -> n+8..15 @k+16B
    const uint32_t b_lm_off = (uint32_t)(ASZ + (warp_n * 64 + ((lane >> 4) * 8) + (lane & 7)) * 112
                                         + ((lane >> 3) & 1) * 16);

    for (int i = 0; i < KT; i++) {
        int w = KT - 1 - i;
        cp_wait(w > 2 ? 2 : w);
        __syncthreads();

        uint32_t stg = sb + (i & 3) * STAGE;
        #pragma unroll
        for (int k16 = 0; k16 < 2; k16++) {
            uint32_t afr[4][4];
            #pragma unroll
            for (int mt = 0; mt < 4; mt++)
                ldsm4(afr[mt], stg + a_lm_off + mt * (16 * 80) + k16 * 32);
            uint32_t bfr[4][4];   // [ntp]: {b0(nt=2p), b1(nt=2p), b0(nt=2p+1), b1(nt=2p+1)}
            #pragma unroll
            for (int ntp = 0; ntp < 4; ntp++)
                ldsm4(bfr[ntp], stg + b_lm_off + ntp * (16 * 112) + k16 * 32);
            #pragma unroll
            for (int mt = 0; mt < 4; mt++)
                #pragma unroll
                for (int nt = 0; nt < 8; nt++)
                    mma16816(acc[mt][nt], afr[mt],
                             bfr[nt >> 1][(nt & 1) * 2], bfr[nt >> 1][(nt & 1) * 2 + 1]);
        }

        if (i + 3 < KT) {
            stsA(i + 3, abuf[(i + 3) & 1]);
            cpB(i + 3);
            cp_commit();
        }
        if (i + 4 < KT) ldgA(i + 4, abuf[(i + 4) & 1]);
    }

    // epilogue
    int m0 = blockIdx.x * 128 + warp_m * 64;
    #pragma unroll
    for (int mt = 0; mt < 4; mt++) {
        #pragma unroll
        for (int nt = 0; nt < 8; nt++) {
            int r = m0 + mt * 16 + g;
            int n = warp_n * 64 + nt * 8 + c * 2;
            if (EPI == 0) {
                *reinterpret_cast<float2*>(outF + (size_t)r * DOUT + n) =
                    make_float2(acc[mt][nt][0], acc[mt][nt][1]);
                *reinterpret_cast<float2*>(outF + (size_t)(r + 8) * DOUT + n) =
                    make_float2(acc[mt][nt][2], acc[mt][nt][3]);
            } else {
                float bn0 = bias[n], bn1 = bias[n + 1];
                outH[(size_t)n * NROWS + r]           = __float2half_rn(acc[mt][nt][0] + bn0);
                outH[(size_t)(n + 1) * NROWS + r]     = __float2half_rn(acc[mt][nt][1] + bn1);
                outH[(size_t)n * NROWS + r + 8]       = __float2half_rn(acc[mt][nt][2] + bn0);
                outH[(size_t)(n + 1) * NROWS + r + 8] = __float2half_rn(acc[mt][nt][3] + bn1);
            }
        }
    }
}

// ---------------- launch ----------------
extern "C" void kernel_launch(void* const* d_in, const int* in_sizes, int n_in,
                              void* d_out, int out_size) {
    const float* X = (const float*)d_in[0];
    const float* A = (const float*)d_in[1];
    const float* W = (const float*)d_in[2];
    const float* b = (const float*)d_in[3];
    float* out = (float*)d_out;

    cudaFuncSetAttribute(gemm_f16<0>, cudaFuncAttributeMaxDynamicSharedMemorySize, SMEM_TOTAL);
    cudaFuncSetAttribute(gemm_f16<1>, cudaFuncAttributeMaxDynamicSharedMemorySize, SMEM_TOTAL);

    void* wt = nullptr; void* ht = nullptr;
    cudaGetSymbolAddress(&wt, g_WT4);
    cudaGetSymbolAddress(&ht, g_HT4);

    pack_w_kernel<<<(DIN * DOUT + 255) / 256, 256>>>(W);
    // H^T = (X @ W + b)^T   (fp16, [256][16384])
    gemm_f16<1><<<128, 256, SMEM_TOTAL>>>(
        X, DIN, (const __half*)wt, DIN, DIN / KC, nullptr, (__half*)ht, b);
    // Out = A_hat @ H
    gemm_f16<0><<<128, 256, SMEM_TOTAL>>>(
        A, NROWS, (const __half*)ht, NROWS, NROWS / KC, out, nullptr, nullptr);
}

// round 4
// speedup vs baseline: 1.5171x; 1.4948x over previous
#include <cuda_runtime.h>
#include <cuda_fp16.h>
#include <cstdint>

#define NROWS 16384
#define DIN   512
#define DOUT  256

// ---- GEMM1 (cp.async style, small) ----
#define KC1 32
#define A1SZ (128 * 80)
#define B1SZ (256 * 112)
#define STG1 (A1SZ + B1SZ)
#define SMEM1 (4 * STG1)

// ---- GEMM2 (bulk-copy style) ----
#define KC2 64
#define KT2 (NROWS / KC2)          // 256
#define A2SZ (128 * 128)           // 16 KB  (128 rows x 64 halfs, 128B rows)
#define B2SZ (256 * 128)           // 32 KB  (256 rows x 64 halfs)
#define STG2 (A2SZ + B2SZ)         // 48 KB
#define SMEM2 (1024 + 4 * STG2)    // 197632 B

// scratch
__device__ uint4 g_WT4[DIN * DOUT / 8];               // W^T fp16 [n][k]
__device__ uint4 g_Hp4[NROWS * DOUT / 8];             // H packed: [kt][256x64 halfs, SW128]
__device__ uint4 g_Ap4[(size_t)NROWS * NROWS / 8];    // A packed: [mc][kt][128x64 halfs, SW128] (512 MiB)

// ---------------- helpers ----------------
__device__ __forceinline__ uint32_t smem_u32(const void* p) {
    uint32_t a;
    asm("{ .reg .u64 t; cvta.to.shared.u64 t, %1; cvt.u32.u64 %0, t; }"
        : "=r"(a) : "l"(p));
    return a;
}
__device__ __forceinline__ void cp_async16(uint32_t dst, const void* src) {
    asm volatile("cp.async.cg.shared.global [%0], [%1], 16;"
                 :: "r"(dst), "l"(src) : "memory");
}
__device__ __forceinline__ void cp_commit() {
    asm volatile("cp.async.commit_group;" ::: "memory");
}
__device__ __forceinline__ void cp_wait(int n) {
    if (n <= 0)      asm volatile("cp.async.wait_group 0;" ::: "memory");
    else if (n == 1) asm volatile("cp.async.wait_group 1;" ::: "memory");
    else             asm volatile("cp.async.wait_group 2;" ::: "memory");
}
__device__ __forceinline__ void sts64(uint32_t a, uint32_t x, uint32_t y) {
    asm volatile("st.shared.v2.b32 [%0], {%1, %2};" :: "r"(a), "r"(x), "r"(y) : "memory");
}
__device__ __forceinline__ uint32_t pack2(float x, float y) {
    __half2 h = __floats2half2_rn(x, y);
    return *reinterpret_cast<uint32_t*>(&h);
}
__device__ __forceinline__ void ldsm4(uint32_t* r, uint32_t addr) {
    asm volatile("ldmatrix.sync.aligned.m8n8.x4.shared.b16 {%0,%1,%2,%3}, [%4];"
                 : "=r"(r[0]), "=r"(r[1]), "=r"(r[2]), "=r"(r[3]) : "r"(addr));
}
__device__ __forceinline__ void mma16816(float* d, const uint32_t* a,
                                         uint32_t b0, uint32_t b1) {
    asm volatile(
        "mma.sync.aligned.m16n8k16.row.col.f32.f16.f16.f32 "
        "{%0,%1,%2,%3}, {%4,%5,%6,%7}, {%8,%9}, {%0,%1,%2,%3};"
        : "+f"(d[0]), "+f"(d[1]), "+f"(d[2]), "+f"(d[3])
        : "r"(a[0]), "r"(a[1]), "r"(a[2]), "r"(a[3]), "r"(b0), "r"(b1));
}
__device__ __forceinline__ void mbar_init(uint32_t addr, uint32_t count) {
    asm volatile("mbarrier.init.shared.b64 [%0], %1;" :: "r"(addr), "r"(count) : "memory");
}
__device__ __forceinline__ void mbar_expect_tx(uint32_t addr, uint32_t bytes) {
    asm volatile("mbarrier.arrive.expect_tx.shared.b64 _, [%0], %1;"
                 :: "r"(addr), "r"(bytes) : "memory");
}
__device__ __forceinline__ void mbar_wait(uint32_t addr, uint32_t parity) {
    asm volatile(
        "{\n\t.reg .pred P;\n\t"
        "W%=:\n\t"
        "mbarrier.try_wait.parity.acquire.cta.shared::cta.b64 P, [%0], %1, 0x989680;\n\t"
        "@!P bra W%=;\n\t"
        "}" :: "r"(addr), "r"(parity) : "memory");
}
__device__ __forceinline__ void bulk_g2s(uint32_t dst, const void* src,
                                         uint32_t bytes, uint32_t mbar) {
    asm volatile(
        "cp.async.bulk.shared::cta.global.mbarrier::complete_tx::bytes [%0], [%1], %2, [%3];"
        :: "r"(dst), "l"(src), "r"(bytes), "r"(mbar) : "memory");
}

// ---------------- W packing: W[k][n] f32 -> WT[n][k] f16 ----------------
__global__ void pack_w_kernel(const float* __restrict__ W) {
    int idx = blockIdx.x * blockDim.x + threadIdx.x;
    if (idx >= DIN * DOUT) return;
    int n = idx / DIN, k = idx % DIN;
    reinterpret_cast<__half*>(g_WT4)[idx] = __float2half_rn(W[(size_t)k * DOUT + n]);
}

// ---------------- A packing: fp32 -> fp16 SW128 tiles ----------------
// tile(mc, kt) = A[mc*128 .. +128][kt*64 .. +64], rows of 128B, SW128 swizzle.
__global__ void pack_a_kernel(const float* __restrict__ A) {
    int kt = blockIdx.x, mc = blockIdx.y;
    int t = threadIdx.x;
    int r = t >> 1, half = t & 1;
    const float4* src = reinterpret_cast<const float4*>(
        A + (size_t)(mc * 128 + r) * NROWS + kt * KC2 + half * 32);
    uint4* tile = g_Ap4 + ((size_t)mc * KT2 + kt) * 1024;   // 16KB / 16B
    #pragma unroll
    for (int jj = 0; jj < 4; jj++) {
        int j16 = half * 4 + jj;
        float4 f0 = src[jj * 2];
        float4 f1 = src[jj * 2 + 1];
        uint4 h;
        h.x = pack2(f0.x, f0.y); h.y = pack2(f0.z, f0.w);
        h.z = pack2(f1.x, f1.y); h.w = pack2(f1.z, f1.w);
        tile[r * 8 + (j16 ^ (r & 7))] = h;
    }
}

// ---------------- GEMM1: H = X @ W + b, output packed SW128 tiles ----------------
__global__ void __launch_bounds__(256, 1)
gemm1_kernel(const float* __restrict__ A, const __half* __restrict__ B,
             const float* __restrict__ bias)
{
    const long long lda = DIN, ldb = DIN;
    const int KT = DIN / KC1;   // 16
    extern __shared__ char sm[];
    const uint32_t sb = smem_u32(sm);
    const int tid = threadIdx.x, lane = tid & 31, wid = tid >> 5;
    const int warp_m = wid & 1, warp_n = wid >> 1;
    const int g = lane >> 2, c = lane & 3;
    const float* aB = A + (size_t)blockIdx.x * 128 * (size_t)lda;

    float abuf[2][16];
    auto ldgA = [&](int kt, float* buf) {
        #pragma unroll
        for (int h = 0; h < 4; h++) {
            int q = tid + h * 256, row = q >> 3, seg = q & 7;
            float4 v = *reinterpret_cast<const float4*>(
                aB + (size_t)row * lda + kt * KC1 + seg * 4);
            buf[h * 4 + 0] = v.x; buf[h * 4 + 1] = v.y;
            buf[h * 4 + 2] = v.z; buf[h * 4 + 3] = v.w;
        }
    };
    auto stsA = [&](int kt, const float* buf) {
        uint32_t st = sb + (kt & 3) * STG1;
        #pragma unroll
        for (int h = 0; h < 4; h++) {
            int q = tid + h * 256, row = q >> 3, seg = q & 7;
            sts64(st + row * 80 + seg * 8,
                  pack2(buf[h * 4 + 0], buf[h * 4 + 1]),
                  pack2(buf[h * 4 + 2], buf[h * 4 + 3]));
        }
    };
    auto cpB = [&](int kt) {
        uint32_t bt = sb + (kt & 3) * STG1 + A1SZ;
        #pragma unroll
        for (int h = 0; h < 4; h++) {
            int q = tid + h * 256, row = q >> 2, seg = q & 3;
            cp_async16(bt + row * 112 + seg * 16,
                       B + (size_t)row * ldb + kt * KC1 + seg * 8);
        }
    };

    for (int kt = 0; kt < 3; kt++) {
        ldgA(kt, abuf[kt & 1]);
        stsA(kt, abuf[kt & 1]);
        cpB(kt);
        cp_commit();
    }
    ldgA(3, abuf[1]);

    float acc[4][8][4];
    #pragma unroll
    for (int mt = 0; mt < 4; mt++)
        #pragma unroll
        for (int nt = 0; nt < 8; nt++)
            #pragma unroll
            for (int e = 0; e < 4; e++) acc[mt][nt][e] = 0.f;

    const uint32_t a_lm_off = (uint32_t)((warp_m * 64 + (lane & 15)) * 80 + (lane >> 4) * 16);
    const uint32_t b_lm_off = (uint32_t)(A1SZ + (warp_n * 64 + ((lane >> 4) * 8) + (lane & 7)) * 112
                                         + ((lane >> 3) & 1) * 16);

    for (int i = 0; i < KT; i++) {
        int w = KT - 1 - i;
        cp_wait(w > 2 ? 2 : w);
        __syncthreads();
        uint32_t stg = sb + (i & 3) * STG1;
        #pragma unroll
        for (int k16 = 0; k16 < 2; k16++) {
            uint32_t afr[4][4];
            #pragma unroll
            for (int mt = 0; mt < 4; mt++)
                ldsm4(afr[mt], stg + a_lm_off + mt * (16 * 80) + k16 * 32);
            uint32_t bfr[4][4];
            #pragma unroll
            for (int ntp = 0; ntp < 4; ntp++)
                ldsm4(bfr[ntp], stg + b_lm_off + ntp * (16 * 112) + k16 * 32);
            #pragma unroll
            for (int mt = 0; mt < 4; mt++)
                #pragma unroll
                for (int nt = 0; nt < 8; nt++)
                    mma16816(acc[mt][nt], afr[mt],
                             bfr[nt >> 1][(nt & 1) * 2], bfr[nt >> 1][(nt & 1) * 2 + 1]);
        }
        if (i + 3 < KT) {
            stsA(i + 3, abuf[(i + 3) & 1]);
            cpB(i + 3);
            cp_commit();
        }
        if (i + 4 < KT) ldgA(i + 4, abuf[(i + 4) & 1]);
    }

    // epilogue: write H packed (tile kt = k/64, 256 rows(n) x 64 halfs, SW128)
    __half* Hp = reinterpret_cast<__half*>(g_Hp4);
    int m0 = blockIdx.x * 128 + warp_m * 64;
    #pragma unroll
    for (int mt = 0; mt < 4; mt++) {
        #pragma unroll
        for (int nt = 0; nt < 8; nt++) {
            int r = m0 + mt * 16 + g;               // global k index of H
            int n = warp_n * 64 + nt * 8 + c * 2;
            float bn0 = bias[n], bn1 = bias[n + 1];
            int kt = r >> 6, kk = r & 63;
            int ch = kk >> 3, w = kk & 7;
            size_t tb = (size_t)kt * 16384;          // halfs per B tile
            int s0 = n & 7, s1 = (n + 1) & 7;
            Hp[tb + n * 64       + ((ch ^ s0) << 3) + w] = __float2half_rn(acc[mt][nt][0] + bn0);
            Hp[tb + (n + 1) * 64 + ((ch ^ s1) << 3) + w] = __float2half_rn(acc[mt][nt][1] + bn1);
            Hp[tb + n * 64       + (((ch + 1) ^ s0) << 3) + w] = __float2half_rn(acc[mt][nt][2] + bn0);
            Hp[tb + (n + 1) * 64 + (((ch + 1) ^ s1) << 3) + w] = __float2half_rn(acc[mt][nt][3] + bn1);
        }
    }
}

// ---------------- GEMM2: Out = A_hat @ H, bulk-copy pipeline ----------------
__global__ void __launch_bounds__(256, 1)
gemm2_kernel(float* __restrict__ out)
{
    extern __shared__ char sm[];
    const uint32_t sb = smem_u32(sm);
    const uint32_t mb = sb;               // 4 mbarriers @ sb+0,8,16,24
    const uint32_t tiles = sb + 1024;
    const int tid = threadIdx.x, lane = tid & 31, wid = tid >> 5;
    const int warp_m = wid & 1, warp_n = wid >> 1;
    const int g = lane >> 2, c = lane & 3;

    if (tid == 0) {
        #pragma unroll
        for (int s = 0; s < 4; s++) mbar_init(mb + 8 * s, 1);
    }
    __syncthreads();

    const uint4* Asrc = g_Ap4 + (size_t)blockIdx.x * KT2 * 1024;
    auto fill = [&](int s, int kt) {
        uint32_t dst = tiles + s * STG2;
        mbar_expect_tx(mb + 8 * s, STG2);
        bulk_g2s(dst, Asrc + (size_t)kt * 1024, A2SZ, mb + 8 * s);
        bulk_g2s(dst + A2SZ, g_Hp4 + (size_t)kt * 2048, B2SZ, mb + 8 * s);
    };
    if (tid == 0) {
        #pragma unroll
        for (int s = 0; s < 4; s++) fill(s, s);
    }

    float acc[4][8][4];
    #pragma unroll
    for (int mt = 0; mt < 4; mt++)
        #pragma unroll
        for (int nt = 0; nt < 8; nt++)
            #pragma unroll
            for (int e = 0; e < 4; e++) acc[mt][nt][e] = 0.f;

    // lane-level ldmatrix addressing (SW128, 128B rows)
    const int arow = lane & 15, ahi = lane >> 4, s7 = lane & 7;
    const int brow = ((lane >> 4) << 3) + (lane & 7), bhi = (lane >> 3) & 1;
    uint32_t a_row_off[4], b_row_off[4];
    #pragma unroll
    for (int mt = 0; mt < 4; mt++)
        a_row_off[mt] = (uint32_t)((warp_m * 64 + mt * 16 + arow) * 128);
    #pragma unroll
    for (int ntp = 0; ntp < 4; ntp++)
        b_row_off[ntp] = (uint32_t)(A2SZ + (warp_n * 64 + ntp * 16 + brow) * 128);

    uint32_t afr[2][4][4], bfr[2][4][4];
    auto load_frags = [&](int buf, int k16, uint32_t stg) {
        uint32_t ja = (uint32_t)(((2 * k16 + ahi) ^ s7) << 4);
        #pragma unroll
        for (int mt = 0; mt < 4; mt++)
            ldsm4(afr[buf][mt], stg + a_row_off[mt] + ja);
        uint32_t jb = (uint32_t)(((2 * k16 + bhi) ^ s7) << 4);
        #pragma unroll
        for (int ntp = 0; ntp < 4; ntp++)
            ldsm4(bfr[buf][ntp], stg + b_row_off[ntp] + jb);
    };

    for (int kt = 0; kt < KT2; kt++) {
        int s = kt & 3, ph = (kt >> 2) & 1;
        mbar_wait(mb + 8 * s, ph);
        uint32_t stg = tiles + s * STG2;
        load_frags(0, 0, stg);
        #pragma unroll
        for (int k16 = 0; k16 < 4; k16++) {
            int cur = k16 & 1;
            if (k16 < 3) load_frags(cur ^ 1, k16 + 1, stg);
            #pragma unroll
            for (int mt = 0; mt < 4; mt++)
                #pragma unroll
                for (int nt = 0; nt < 8; nt++)
                    mma16816(acc[mt][nt], afr[cur][mt],
                             bfr[cur][nt >> 1][(nt & 1) * 2],
                             bfr[cur][nt >> 1][(nt & 1) * 2 + 1]);
        }
        __syncthreads();
        if (tid == 0 && kt + 4 < KT2) fill(s, kt + 4);
    }

    // epilogue: f32 row-major out
    int m0 = blockIdx.x * 128 + warp_m * 64;
    #pragma unroll
    for (int mt = 0; mt < 4; mt++) {
        #pragma unroll
        for (int nt = 0; nt < 8; nt++) {
            int r = m0 + mt * 16 + g;
            int n = warp_n * 64 + nt * 8 + c * 2;
            *reinterpret_cast<float2*>(out + (size_t)r * DOUT + n) =
                make_float2(acc[mt][nt][0], acc[mt][nt][1]);
            *reinterpret_cast<float2*>(out + (size_t)(r + 8) * DOUT + n) =
                make_float2(acc[mt][nt][2], acc[mt][nt][3]);
        }
    }
}

// ---------------- launch ----------------
extern "C" void kernel_launch(void* const* d_in, const int* in_sizes, int n_in,
                              void* d_out, int out_size) {
    const float* X = (const float*)d_in[0];
    const float* A = (const float*)d_in[1];
    const float* W = (const float*)d_in[2];
    const float* b = (const float*)d_in[3];
    float* out = (float*)d_out;

    cudaFuncSetAttribute(gemm1_kernel, cudaFuncAttributeMaxDynamicSharedMemorySize, SMEM1);
    cudaFuncSetAttribute(gemm2_kernel, cudaFuncAttributeMaxDynamicSharedMemorySize, SMEM2);

    void* wt = nullptr;
    cudaGetSymbolAddress(&wt, g_WT4);

    pack_w_kernel<<<(DIN * DOUT + 255) / 256, 256>>>(W);
    pack_a_kernel<<<dim3(KT2, 128), 256>>>(A);
    gemm1_kernel<<<128, 256, SMEM1>>>(X, (const __half*)wt, b);
    gemm2_kernel<<<128, 256, SMEM2>>>(out);
}

// round 5
// speedup vs baseline: 1.5197x; 1.0017x over previous
#include <cuda_runtime.h>
#include <cuda_fp16.h>
#include <cstdint>

#define NROWS 16384
#define DIN   512
#define DOUT  256

// ---- GEMM1 (cp.async style, small) ----
#define KC1 32
#define A1SZ (128 * 80)
#define B1SZ (256 * 112)
#define STG1 (A1SZ + B1SZ)
#define SMEM1 (4 * STG1)

// ---- GEMM2 (bulk-copy, warp-specialized) ----
#define KC2 64
#define KT2 (NROWS / KC2)          // 256
#define A2SZ (128 * 128)           // 16 KB
#define B2SZ (256 * 128)           // 32 KB
#define STG2 (A2SZ + B2SZ)         // 48 KB
#define SMEM2 (1024 + 4 * STG2)

// scratch
__device__ uint4 g_WT4[DIN * DOUT / 8];               // W^T fp16 [n][k]
__device__ uint4 g_Hp4[NROWS * DOUT / 8];             // H packed: [kt][256x64 halfs, SW128]
__device__ uint4 g_Ap4[(size_t)NROWS * NROWS / 8];    // A packed: [mc][kt][128x64, SW128]

// ---------------- helpers ----------------
__device__ __forceinline__ uint32_t smem_u32(const void* p) {
    uint32_t a;
    asm("{ .reg .u64 t; cvta.to.shared.u64 t, %1; cvt.u32.u64 %0, t; }"
        : "=r"(a) : "l"(p));
    return a;
}
__device__ __forceinline__ void cp_async16(uint32_t dst, const void* src) {
    asm volatile("cp.async.cg.shared.global [%0], [%1], 16;"
                 :: "r"(dst), "l"(src) : "memory");
}
__device__ __forceinline__ void cp_commit() {
    asm volatile("cp.async.commit_group;" ::: "memory");
}
__device__ __forceinline__ void cp_wait(int n) {
    if (n <= 0)      asm volatile("cp.async.wait_group 0;" ::: "memory");
    else if (n == 1) asm volatile("cp.async.wait_group 1;" ::: "memory");
    else             asm volatile("cp.async.wait_group 2;" ::: "memory");
}
__device__ __forceinline__ void sts64(uint32_t a, uint32_t x, uint32_t y) {
    asm volatile("st.shared.v2.b32 [%0], {%1, %2};" :: "r"(a), "r"(x), "r"(y) : "memory");
}
__device__ __forceinline__ uint32_t pack2(float x, float y) {
    __half2 h = __floats2half2_rn(x, y);
    return *reinterpret_cast<uint32_t*>(&h);
}
__device__ __forceinline__ void ldsm4(uint32_t* r, uint32_t addr) {
    asm volatile("ldmatrix.sync.aligned.m8n8.x4.shared.b16 {%0,%1,%2,%3}, [%4];"
                 : "=r"(r[0]), "=r"(r[1]), "=r"(r[2]), "=r"(r[3]) : "r"(addr));
}
__device__ __forceinline__ void mma16816(float* d, const uint32_t* a,
                                         uint32_t b0, uint32_t b1) {
    asm volatile(
        "mma.sync.aligned.m16n8k16.row.col.f32.f16.f16.f32 "
        "{%0,%1,%2,%3}, {%4,%5,%6,%7}, {%8,%9}, {%0,%1,%2,%3};"
        : "+f"(d[0]), "+f"(d[1]), "+f"(d[2]), "+f"(d[3])
        : "r"(a[0]), "r"(a[1]), "r"(a[2]), "r"(a[3]), "r"(b0), "r"(b1));
}
__device__ __forceinline__ void mbar_init(uint32_t addr, uint32_t count) {
    asm volatile("mbarrier.init.shared.b64 [%0], %1;" :: "r"(addr), "r"(count) : "memory");
}
__device__ __forceinline__ void mbar_expect_tx(uint32_t addr, uint32_t bytes) {
    asm volatile("mbarrier.arrive.expect_tx.shared.b64 _, [%0], %1;"
                 :: "r"(addr), "r"(bytes) : "memory");
}
__device__ __forceinline__ void mbar_arrive(uint32_t addr) {
    asm volatile("mbarrier.arrive.shared.b64 _, [%0];" :: "r"(addr) : "memory");
}
__device__ __forceinline__ void mbar_wait(uint32_t addr, uint32_t parity) {
    asm volatile(
        "{\n\t.reg .pred P;\n\t"
        "W%=:\n\t"
        "mbarrier.try_wait.parity.acquire.cta.shared::cta.b64 P, [%0], %1, 0x989680;\n\t"
        "@!P bra W%=;\n\t"
        "}" :: "r"(addr), "r"(parity) : "memory");
}
__device__ __forceinline__ void bulk_g2s(uint32_t dst, const void* src,
                                         uint32_t bytes, uint32_t mbar) {
    asm volatile(
        "cp.async.bulk.shared::cta.global.mbarrier::complete_tx::bytes [%0], [%1], %2, [%3];"
        :: "r"(dst), "l"(src), "r"(bytes), "r"(mbar) : "memory");
}

// ---------------- W packing ----------------
__global__ void pack_w_kernel(const float* __restrict__ W) {
    int idx = blockIdx.x * blockDim.x + threadIdx.x;
    if (idx >= DIN * DOUT) return;
    int n = idx / DIN, k = idx % DIN;
    reinterpret_cast<__half*>(g_WT4)[idx] = __float2half_rn(W[(size_t)k * DOUT + n]);
}

// ---------------- A packing: fp32 -> fp16 SW128 tiles ----------------
__global__ void pack_a_kernel(const float* __restrict__ A) {
    int kt = blockIdx.x, mc = blockIdx.y;
    int t = threadIdx.x;
    int r = t >> 1, half = t & 1;
    const float4* src = reinterpret_cast<const float4*>(
        A + (size_t)(mc * 128 + r) * NROWS + kt * KC2 + half * 32);
    uint4* tile = g_Ap4 + ((size_t)mc * KT2 + kt) * 1024;
    #pragma unroll
    for (int jj = 0; jj < 4; jj++) {
        int j16 = half * 4 + jj;
        float4 f0 = src[jj * 2];
        float4 f1 = src[jj * 2 + 1];
        uint4 h;
        h.x = pack2(f0.x, f0.y); h.y = pack2(f0.z, f0.w);
        h.z = pack2(f1.x, f1.y); h.w = pack2(f1.z, f1.w);
        tile[r * 8 + (j16 ^ (r & 7))] = h;
    }
}

// ---------------- GEMM1: H = X @ W + b -> packed SW128 tiles ----------------
__global__ void __launch_bounds__(256, 1)
gemm1_kernel(const float* __restrict__ A, const __half* __restrict__ B,
             const float* __restrict__ bias)
{
    const long long lda = DIN, ldb = DIN;
    const int KT = DIN / KC1;
    extern __shared__ char sm[];
    const uint32_t sb = smem_u32(sm);
    const int tid = threadIdx.x, lane = tid & 31, wid = tid >> 5;
    const int warp_m = wid & 1, warp_n = wid >> 1;
    const int g = lane >> 2, c = lane & 3;
    const float* aB = A + (size_t)blockIdx.x * 128 * (size_t)lda;

    float abuf[2][16];
    auto ldgA = [&](int kt, float* buf) {
        #pragma unroll
        for (int h = 0; h < 4; h++) {
            int q = tid + h * 256, row = q >> 3, seg = q & 7;
            float4 v = *reinterpret_cast<const float4*>(
                aB + (size_t)row * lda + kt * KC1 + seg * 4);
            buf[h * 4 + 0] = v.x; buf[h * 4 + 1] = v.y;
            buf[h * 4 + 2] = v.z; buf[h * 4 + 3] = v.w;
        }
    };
    auto stsA = [&](int kt, const float* buf) {
        uint32_t st = sb + (kt & 3) * STG1;
        #pragma unroll
        for (int h = 0; h < 4; h++) {
            int q = tid + h * 256, row = q >> 3, seg = q & 7;
            sts64(st + row * 80 + seg * 8,
                  pack2(buf[h * 4 + 0], buf[h * 4 + 1]),
                  pack2(buf[h * 4 + 2], buf[h * 4 + 3]));
        }
    };
    auto cpB = [&](int kt) {
        uint32_t bt = sb + (kt & 3) * STG1 + A1SZ;
        #pragma unroll
        for (int h = 0; h < 4; h++) {
            int q = tid + h * 256, row = q >> 2, seg = q & 3;
            cp_async16(bt + row * 112 + seg * 16,
                       B + (size_t)row * ldb + kt * KC1 + seg * 8);
        }
    };

    for (int kt = 0; kt < 3; kt++) {
        ldgA(kt, abuf[kt & 1]);
        stsA(kt, abuf[kt & 1]);
        cpB(kt);
        cp_commit();
    }
    ldgA(3, abuf[1]);

    float acc[4][8][4];
    #pragma unroll
    for (int mt = 0; mt < 4; mt++)
        #pragma unroll
        for (int nt = 0; nt < 8; nt++)
            #pragma unroll
            for (int e = 0; e < 4; e++) acc[mt][nt][e] = 0.f;

    const uint32_t a_lm_off = (uint32_t)((warp_m * 64 + (lane & 15)) * 80 + (lane >> 4) * 16);
    const uint32_t b_lm_off = (uint32_t)(A1SZ + (warp_n * 64 + ((lane >> 4) * 8) + (lane & 7)) * 112
                                         + ((lane >> 3) & 1) * 16);

    for (int i = 0; i < KT; i++) {
        int w = KT - 1 - i;
        cp_wait(w > 2 ? 2 : w);
        __syncthreads();
        uint32_t stg = sb + (i & 3) * STG1;
        #pragma unroll
        for (int k16 = 0; k16 < 2; k16++) {
            uint32_t afr[4][4];
            #pragma unroll
            for (int mt = 0; mt < 4; mt++)
                ldsm4(afr[mt], stg + a_lm_off + mt * (16 * 80) + k16 * 32);
            uint32_t bfr[4][4];
            #pragma unroll
            for (int ntp = 0; ntp < 4; ntp++)
                ldsm4(bfr[ntp], stg + b_lm_off + ntp * (16 * 112) + k16 * 32);
            #pragma unroll
            for (int mt = 0; mt < 4; mt++)
                #pragma unroll
                for (int nt = 0; nt < 8; nt++)
                    mma16816(acc[mt][nt], afr[mt],
                             bfr[nt >> 1][(nt & 1) * 2], bfr[nt >> 1][(nt & 1) * 2 + 1]);
        }
        if (i + 3 < KT) {
            stsA(i + 3, abuf[(i + 3) & 1]);
            cpB(i + 3);
            cp_commit();
        }
        if (i + 4 < KT) ldgA(i + 4, abuf[(i + 4) & 1]);
    }

    __half* Hp = reinterpret_cast<__half*>(g_Hp4);
    int m0 = blockIdx.x * 128 + warp_m * 64;
    #pragma unroll
    for (int mt = 0; mt < 4; mt++) {
        #pragma unroll
        for (int nt = 0; nt < 8; nt++) {
            int r = m0 + mt * 16 + g;
            int n = warp_n * 64 + nt * 8 + c * 2;
            float bn0 = bias[n], bn1 = bias[n + 1];
            int kt = r >> 6, kk = r & 63;
            int ch = kk >> 3, w = kk & 7;
            size_t tb = (size_t)kt * 16384;
            int s0 = n & 7, s1 = (n + 1) & 7;
            Hp[tb + n * 64       + ((ch ^ s0) << 3) + w] = __float2half_rn(acc[mt][nt][0] + bn0);
            Hp[tb + (n + 1) * 64 + ((ch ^ s1) << 3) + w] = __float2half_rn(acc[mt][nt][1] + bn1);
            Hp[tb + n * 64       + (((ch + 1) ^ s0) << 3) + w] = __float2half_rn(acc[mt][nt][2] + bn0);
            Hp[tb + (n + 1) * 64 + (((ch + 1) ^ s1) << 3) + w] = __float2half_rn(acc[mt][nt][3] + bn1);
        }
    }
}

// ---------------- GEMM2: warp-specialized producer/consumer ----------------
// full[s] @ mb+8s (tx), empty[s] @ mb+32+8s (count=8)
__global__ void __launch_bounds__(288, 1)
gemm2_kernel(float* __restrict__ out)
{
    extern __shared__ char sm[];
    const uint32_t sb = smem_u32(sm);
    const uint32_t mb = sb;
    const uint32_t tiles = sb + 1024;
    const int tid = threadIdx.x, lane = tid & 31, wid = tid >> 5;

    if (tid == 0) {
        #pragma unroll
        for (int s = 0; s < 4; s++) {
            mbar_init(mb + 8 * s, 1);        // full
            mbar_init(mb + 32 + 8 * s, 8);   // empty
        }
    }
    __syncthreads();

    if (wid == 8) {
        // ---- producer warp ----
        if (lane == 0) {
            const uint4* Asrc = g_Ap4 + (size_t)blockIdx.x * KT2 * 1024;
            for (int kt = 0; kt < KT2; kt++) {
                int s = kt & 3, wrap = kt >> 2;
                if (kt >= 4) mbar_wait(mb + 32 + 8 * s, (wrap - 1) & 1);
                uint32_t dst = tiles + s * STG2;
                mbar_expect_tx(mb + 8 * s, STG2);
                bulk_g2s(dst, Asrc + (size_t)kt * 1024, A2SZ, mb + 8 * s);
                bulk_g2s(dst + A2SZ, g_Hp4 + (size_t)kt * 2048, B2SZ, mb + 8 * s);
            }
        }
        return;
    }

    // ---- compute warps (0..7) ----
    const int warp_m = wid & 1, warp_n = wid >> 1;
    const int g = lane >> 2, c = lane & 3;

    float acc[4][8][4];
    #pragma unroll
    for (int mt = 0; mt < 4; mt++)
        #pragma unroll
        for (int nt = 0; nt < 8; nt++)
            #pragma unroll
            for (int e = 0; e < 4; e++) acc[mt][nt][e] = 0.f;

    const int arow = lane & 15, ahi = lane >> 4, s7 = lane & 7;
    const int brow = ((lane >> 4) << 3) + (lane & 7), bhi = (lane >> 3) & 1;
    uint32_t a_row_off[4], b_row_off[4];
    #pragma unroll
    for (int mt = 0; mt < 4; mt++)
        a_row_off[mt] = (uint32_t)((warp_m * 64 + mt * 16 + arow) * 128);
    #pragma unroll
    for (int ntp = 0; ntp < 4; ntp++)
        b_row_off[ntp] = (uint32_t)(A2SZ + (warp_n * 64 + ntp * 16 + brow) * 128);

    uint32_t afr[2][4][4], bfr[2][4][4];
    auto load_frags = [&](int buf, int k16, uint32_t stg) {
        uint32_t ja = (uint32_t)(((2 * k16 + ahi) ^ s7) << 4);
        #pragma unroll
        for (int mt = 0; mt < 4; mt++)
            ldsm4(afr[buf][mt], stg + a_row_off[mt] + ja);
        uint32_t jb = (uint32_t)(((2 * k16 + bhi) ^ s7) << 4);
        #pragma unroll
        for (int ntp = 0; ntp < 4; ntp++)
            ldsm4(bfr[buf][ntp], stg + b_row_off[ntp] + jb);
    };

    for (int kt = 0; kt < KT2; kt++) {
        int s = kt & 3, ph = (kt >> 2) & 1;
        mbar_wait(mb + 8 * s, ph);
        uint32_t stg = tiles + s * STG2;
        load_frags(0, 0, stg);
        #pragma unroll
        for (int k16 = 0; k16 < 4; k16++) {
            int cur = k16 & 1;
            if (k16 < 3) load_frags(cur ^ 1, k16 + 1, stg);
            #pragma unroll
            for (int mt = 0; mt < 4; mt++)
                #pragma unroll
                for (int nt = 0; nt < 8; nt++)
                    mma16816(acc[mt][nt], afr[cur][mt],
                             bfr[cur][nt >> 1][(nt & 1) * 2],
                             bfr[cur][nt >> 1][(nt & 1) * 2 + 1]);
        }
        if (lane == 0) mbar_arrive(mb + 32 + 8 * s);   // stage consumed
    }

    int m0 = blockIdx.x * 128 + warp_m * 64;
    #pragma unroll
    for (int mt = 0; mt < 4; mt++) {
        #pragma unroll
        for (int nt = 0; nt < 8; nt++) {
            int r = m0 + mt * 16 + g;
            int n = warp_n * 64 + nt * 8 + c * 2;
            *reinterpret_cast<float2*>(out + (size_t)r * DOUT + n) =
                make_float2(acc[mt][nt][0], acc[mt][nt][1]);
            *reinterpret_cast<float2*>(out + (size_t)(r + 8) * DOUT + n) =
                make_float2(acc[mt][nt][2], acc[mt][nt][3]);
        }
    }
}

// ---------------- launch ----------------
extern "C" void kernel_launch(void* const* d_in, const int* in_sizes, int n_in,
                              void* d_out, int out_size) {
    const float* X = (const float*)d_in[0];
    const float* A = (const float*)d_in[1];
    const float* W = (const float*)d_in[2];
    const float* b = (const float*)d_in[3];
    float* out = (float*)d_out;

    cudaFuncSetAttribute(gemm1_kernel, cudaFuncAttributeMaxDynamicSharedMemorySize, SMEM1);
    cudaFuncSetAttribute(gemm2_kernel, cudaFuncAttributeMaxDynamicSharedMemorySize, SMEM2);

    void* wt = nullptr;
    cudaGetSymbolAddress(&wt, g_WT4);

    pack_w_kernel<<<(DIN * DOUT + 255) / 256, 256>>>(W);
    pack_a_kernel<<<dim3(KT2, 128), 256>>>(A);
    gemm1_kernel<<<128, 256, SMEM1>>>(X, (const __half*)wt, b);
    gemm2_kernel<<<128, 288, SMEM2>>>(out);
}

// round 6
// speedup vs baseline: 2.2888x; 1.5061x over previous
#include <cuda_runtime.h>
#include <cuda_fp16.h>
#include <cstdint>

#define NROWS 16384
#define DIN   512
#define DOUT  256

// ---- GEMM1 (cp.async style, small) ----
#define KC1 32
#define A1SZ (128 * 80)
#define B1SZ (256 * 112)
#define STG1 (A1SZ + B1SZ)
#define SMEM1 (4 * STG1)

// ---- GEMM2 (fused convert + bulk-copy, warp-specialized) ----
#define KC2 64
#define KT2 (NROWS / KC2)          // 256
#define A2SZ (128 * 128)           // 16 KB  (fp16 SW128)
#define B2SZ (256 * 128)           // 32 KB
#define STG2 (A2SZ + B2SZ)         // 48 KB
#define SMEM2 (1024 + 4 * STG2)

// scratch
__device__ uint4 g_WT4[DIN * DOUT / 8];    // W^T fp16 [n][k]
__device__ uint4 g_Hp4[NROWS * DOUT / 8];  // H packed: [kt][256x64 halfs, SW128]

// ---------------- helpers ----------------
__device__ __forceinline__ uint32_t smem_u32(const void* p) {
    uint32_t a;
    asm("{ .reg .u64 t; cvta.to.shared.u64 t, %1; cvt.u32.u64 %0, t; }"
        : "=r"(a) : "l"(p));
    return a;
}
__device__ __forceinline__ void cp_async16(uint32_t dst, const void* src) {
    asm volatile("cp.async.cg.shared.global [%0], [%1], 16;"
                 :: "r"(dst), "l"(src) : "memory");
}
__device__ __forceinline__ void cp_commit() {
    asm volatile("cp.async.commit_group;" ::: "memory");
}
__device__ __forceinline__ void cp_wait(int n) {
    if (n <= 0)      asm volatile("cp.async.wait_group 0;" ::: "memory");
    else if (n == 1) asm volatile("cp.async.wait_group 1;" ::: "memory");
    else             asm volatile("cp.async.wait_group 2;" ::: "memory");
}
__device__ __forceinline__ void sts64(uint32_t a, uint32_t x, uint32_t y) {
    asm volatile("st.shared.v2.b32 [%0], {%1, %2};" :: "r"(a), "r"(x), "r"(y) : "memory");
}
__device__ __forceinline__ uint32_t pack2(float x, float y) {
    __half2 h = __floats2half2_rn(x, y);
    return *reinterpret_cast<uint32_t*>(&h);
}
__device__ __forceinline__ void ldsm4(uint32_t* r, uint32_t addr) {
    asm volatile("ldmatrix.sync.aligned.m8n8.x4.shared.b16 {%0,%1,%2,%3}, [%4];"
                 : "=r"(r[0]), "=r"(r[1]), "=r"(r[2]), "=r"(r[3]) : "r"(addr));
}
__device__ __forceinline__ void mma16816(float* d, const uint32_t* a,
                                         uint32_t b0, uint32_t b1) {
    asm volatile(
        "mma.sync.aligned.m16n8k16.row.col.f32.f16.f16.f32 "
        "{%0,%1,%2,%3}, {%4,%5,%6,%7}, {%8,%9}, {%0,%1,%2,%3};"
        : "+f"(d[0]), "+f"(d[1]), "+f"(d[2]), "+f"(d[3])
        : "r"(a[0]), "r"(a[1]), "r"(a[2]), "r"(a[3]), "r"(b0), "r"(b1));
}
__device__ __forceinline__ void mbar_init(uint32_t addr, uint32_t count) {
    asm volatile("mbarrier.init.shared.b64 [%0], %1;" :: "r"(addr), "r"(count) : "memory");
}
__device__ __forceinline__ void mbar_expect_tx(uint32_t addr, uint32_t bytes) {
    asm volatile("mbarrier.arrive.expect_tx.shared.b64 _, [%0], %1;"
                 :: "r"(addr), "r"(bytes) : "memory");
}
__device__ __forceinline__ void mbar_arrive(uint32_t addr) {
    asm volatile("mbarrier.arrive.release.cta.shared.b64 _, [%0];" :: "r"(addr) : "memory");
}
__device__ __forceinline__ void mbar_wait(uint32_t addr, uint32_t parity) {
    asm volatile(
        "{\n\t.reg .pred P;\n\t"
        "W%=:\n\t"
        "mbarrier.try_wait.parity.acquire.cta.shared::cta.b64 P, [%0], %1, 0x989680;\n\t"
        "@!P bra W%=;\n\t"
        "}" :: "r"(addr), "r"(parity) : "memory");
}
__device__ __forceinline__ void bulk_g2s(uint32_t dst, const void* src,
                                         uint32_t bytes, uint32_t mbar) {
    asm volatile(
        "cp.async.bulk.shared::cta.global.mbarrier::complete_tx::bytes [%0], [%1], %2, [%3];"
        :: "r"(dst), "l"(src), "r"(bytes), "r"(mbar) : "memory");
}

// ---------------- W packing ----------------
__global__ void pack_w_kernel(const float* __restrict__ W) {
    int idx = blockIdx.x * blockDim.x + threadIdx.x;
    if (idx >= DIN * DOUT) return;
    int n = idx / DIN, k = idx % DIN;
    reinterpret_cast<__half*>(g_WT4)[idx] = __float2half_rn(W[(size_t)k * DOUT + n]);
}

// ---------------- GEMM1: H = X @ W + b -> packed SW128 tiles ----------------
__global__ void __launch_bounds__(256, 1)
gemm1_kernel(const float* __restrict__ A, const __half* __restrict__ B,
             const float* __restrict__ bias)
{
    const long long lda = DIN, ldb = DIN;
    const int KT = DIN / KC1;
    extern __shared__ char sm[];
    const uint32_t sb = smem_u32(sm);
    const int tid = threadIdx.x, lane = tid & 31, wid = tid >> 5;
    const int warp_m = wid & 1, warp_n = wid >> 1;
    const int g = lane >> 2, c = lane & 3;
    const float* aB = A + (size_t)blockIdx.x * 128 * (size_t)lda;

    float abuf[2][16];
    auto ldgA = [&](int kt, float* buf) {
        #pragma unroll
        for (int h = 0; h < 4; h++) {
            int q = tid + h * 256, row = q >> 3, seg = q & 7;
            float4 v = *reinterpret_cast<const float4*>(
                aB + (size_t)row * lda + kt * KC1 + seg * 4);
            buf[h * 4 + 0] = v.x; buf[h * 4 + 1] = v.y;
            buf[h * 4 + 2] = v.z; buf[h * 4 + 3] = v.w;
        }
    };
    auto stsA = [&](int kt, const float* buf) {
        uint32_t st = sb + (kt & 3) * STG1;
        #pragma unroll
        for (int h = 0; h < 4; h++) {
            int q = tid + h * 256, row = q >> 3, seg = q & 7;
            sts64(st + row * 80 + seg * 8,
                  pack2(buf[h * 4 + 0], buf[h * 4 + 1]),
                  pack2(buf[h * 4 + 2], buf[h * 4 + 3]));
        }
    };
    auto cpB = [&](int kt) {
        uint32_t bt = sb + (kt & 3) * STG1 + A1SZ;
        #pragma unroll
        for (int h = 0; h < 4; h++) {
            int q = tid + h * 256, row = q >> 2, seg = q & 3;
            cp_async16(bt + row * 112 + seg * 16,
                       B + (size_t)row * ldb + kt * KC1 + seg * 8);
        }
    };

    for (int kt = 0; kt < 3; kt++) {
        ldgA(kt, abuf[kt & 1]);
        stsA(kt, abuf[kt & 1]);
        cpB(kt);
        cp_commit();
    }
    ldgA(3, abuf[1]);

    float acc[4][8][4];
    #pragma unroll
    for (int mt = 0; mt < 4; mt++)
        #pragma unroll
        for (int nt = 0; nt < 8; nt++)
            #pragma unroll
            for (int e = 0; e < 4; e++) acc[mt][nt][e] = 0.f;

    const uint32_t a_lm_off = (uint32_t)((warp_m * 64 + (lane & 15)) * 80 + (lane >> 4) * 16);
    const uint32_t b_lm_off = (uint32_t)(A1SZ + (warp_n * 64 + ((lane >> 4) * 8) + (lane & 7)) * 112
                                         + ((lane >> 3) & 1) * 16);

    for (int i = 0; i < KT; i++) {
        int w = KT - 1 - i;
        cp_wait(w > 2 ? 2 : w);
        __syncthreads();
        uint32_t stg = sb + (i & 3) * STG1;
        #pragma unroll
        for (int k16 = 0; k16 < 2; k16++) {
            uint32_t afr[4][4];
            #pragma unroll
            for (int mt = 0; mt < 4; mt++)
                ldsm4(afr[mt], stg + a_lm_off + mt * (16 * 80) + k16 * 32);
            uint32_t bfr[4][4];
            #pragma unroll
            for (int ntp = 0; ntp < 4; ntp++)
                ldsm4(bfr[ntp], stg + b_lm_off + ntp * (16 * 112) + k16 * 32);
            #pragma unroll
            for (int mt = 0; mt < 4; mt++)
                #pragma unroll
                for (int nt = 0; nt < 8; nt++)
                    mma16816(acc[mt][nt], afr[mt],
                             bfr[nt >> 1][(nt & 1) * 2], bfr[nt >> 1][(nt & 1) * 2 + 1]);
        }
        if (i + 3 < KT) {
            stsA(i + 3, abuf[(i + 3) & 1]);
            cpB(i + 3);
            cp_commit();
        }
        if (i + 4 < KT) ldgA(i + 4, abuf[(i + 4) & 1]);
    }

    __half* Hp = reinterpret_cast<__half*>(g_Hp4);
    int m0 = blockIdx.x * 128 + warp_m * 64;
    #pragma unroll
    for (int mt = 0; mt < 4; mt++) {
        #pragma unroll
        for (int nt = 0; nt < 8; nt++) {
            int r = m0 + mt * 16 + g;
            int n = warp_n * 64 + nt * 8 + c * 2;
            float bn0 = bias[n], bn1 = bias[n + 1];
            int kt = r >> 6, kk = r & 63;
            int ch = kk >> 3, w = kk & 7;
            size_t tb = (size_t)kt * 16384;
            int s0 = n & 7, s1 = (n + 1) & 7;
            Hp[tb + n * 64       + ((ch ^ s0) << 3) + w] = __float2half_rn(acc[mt][nt][0] + bn0);
            Hp[tb + (n + 1) * 64 + ((ch ^ s1) << 3) + w] = __float2half_rn(acc[mt][nt][1] + bn1);
            Hp[tb + n * 64       + (((ch + 1) ^ s0) << 3) + w] = __float2half_rn(acc[mt][nt][2] + bn0);
            Hp[tb + (n + 1) * 64 + (((ch + 1) ^ s1) << 3) + w] = __float2half_rn(acc[mt][nt][3] + bn1);
        }
    }
}

// ---------------- GEMM2: Out = A_hat @ H, fused fp32->fp16 convert ----------------
// Warps 0-7: compute (64x64 tiles). Warps 8-11: convert A (32 rows each).
// full[s] @ mb+8s: count = 128 convert-lane arrives + 1 expect_tx arrive (B bulk)
// empty[s] @ mb+32+8s: count = 8 (compute warps)
__global__ void __launch_bounds__(384, 1)
gemm2_kernel(const float* __restrict__ Ahat, float* __restrict__ out)
{
    extern __shared__ char sm[];
    const uint32_t sb = smem_u32(sm);
    const uint32_t mb = sb;
    const uint32_t tiles = sb + 1024;
    const int tid = threadIdx.x, lane = tid & 31, wid = tid >> 5;

    if (tid == 0) {
        #pragma unroll
        for (int s = 0; s < 4; s++) {
            mbar_init(mb + 8 * s, 129);      // full: 128 lanes + 1 tx-arrive
            mbar_init(mb + 32 + 8 * s, 8);   // empty
        }
    }
    __syncthreads();

    if (wid >= 8) {
        // ---- convert-producer warps (A: fp32 gmem -> fp16 SW128 smem) ----
        const int w = wid - 8;
        const int lane4 = lane & 15, rh = lane >> 4;
        const int r0 = w * 32 + rh;                       // rows r0, r0+2, ..., r0+30
        const float* src0 = Ahat + (size_t)(blockIdx.x * 128 + r0) * NROWS + lane4 * 4;
        // smem placement for this lane's 8 bytes within a 128B row
        const uint32_t j16 = (uint32_t)(lane4 >> 1);
        const uint32_t low8 = (uint32_t)((lane4 & 1) * 8);

        for (int kt = 0; kt < KT2; kt++) {
            int s = kt & 3, wrap = kt >> 2;
            if (kt >= 4) mbar_wait(mb + 32 + 8 * s, (wrap - 1) & 1);
            uint32_t stg = tiles + s * STG2;
            if (wid == 8 && lane == 0) {
                mbar_expect_tx(mb + 8 * s, B2SZ);
                bulk_g2s(stg + A2SZ, g_Hp4 + (size_t)kt * 2048, B2SZ, mb + 8 * s);
            }
            const float* srck = src0 + kt * KC2;
            #pragma unroll
            for (int it = 0; it < 16; it++) {
                int r = r0 + 2 * it;
                float4 v = *reinterpret_cast<const float4*>(srck + (size_t)(2 * it) * NROWS);
                uint32_t off = (uint32_t)(r * 128) + (((j16 ^ (uint32_t)(r & 7)) << 4) + low8);
                sts64(stg + off, pack2(v.x, v.y), pack2(v.z, v.w));
            }
            mbar_arrive(mb + 8 * s);   // per-lane release arrive
        }
        return;
    }

    // ---- compute warps (0..7) ----
    const int warp_m = wid & 1, warp_n = wid >> 1;
    const int g = lane >> 2, c = lane & 3;

    float acc[4][8][4];
    #pragma unroll
    for (int mt = 0; mt < 4; mt++)
        #pragma unroll
        for (int nt = 0; nt < 8; nt++)
            #pragma unroll
            for (int e = 0; e < 4; e++) acc[mt][nt][e] = 0.f;

    const int arow = lane & 15, ahi = lane >> 4, s7 = lane & 7;
    const int brow = ((lane >> 4) << 3) + (lane & 7), bhi = (lane >> 3) & 1;
    uint32_t a_row_off[4], b_row_off[4];
    #pragma unroll
    for (int mt = 0; mt < 4; mt++)
        a_row_off[mt] = (uint32_t)((warp_m * 64 + mt * 16 + arow) * 128);
    #pragma unroll
    for (int ntp = 0; ntp < 4; ntp++)
        b_row_off[ntp] = (uint32_t)(A2SZ + (warp_n * 64 + ntp * 16 + brow) * 128);

    uint32_t afr[2][4][4], bfr[2][4][4];
    auto load_frags = [&](int buf, int k16, uint32_t stg) {
        uint32_t ja = (uint32_t)(((2 * k16 + ahi) ^ s7) << 4);
        #pragma unroll
        for (int mt = 0; mt < 4; mt++)
            ldsm4(afr[buf][mt], stg + a_row_off[mt] + ja);
        uint32_t jb = (uint32_t)(((2 * k16 + bhi) ^ s7) << 4);
        #pragma unroll
        for (int ntp = 0; ntp < 4; ntp++)
            ldsm4(bfr[buf][ntp], stg + b_row_off[ntp] + jb);
    };

    for (int kt = 0; kt < KT2; kt++) {
        int s = kt & 3, ph = (kt >> 2) & 1;
        mbar_wait(mb + 8 * s, ph);
        uint32_t stg = tiles + s * STG2;
        load_frags(0, 0, stg);
        #pragma unroll
        for (int k16 = 0; k16 < 4; k16++) {
            int cur = k16 & 1;
            if (k16 < 3) load_frags(cur ^ 1, k16 + 1, stg);
            #pragma unroll
            for (int mt = 0; mt < 4; mt++)
                #pragma unroll
                for (int nt = 0; nt < 8; nt++)
                    mma16816(acc[mt][nt], afr[cur][mt],
                             bfr[cur][nt >> 1][(nt & 1) * 2],
                             bfr[cur][nt >> 1][(nt & 1) * 2 + 1]);
        }
        if (lane == 0) mbar_arrive(mb + 32 + 8 * s);   // stage consumed
    }

    int m0 = blockIdx.x * 128 + warp_m * 64;
    #pragma unroll
    for (int mt = 0; mt < 4; mt++) {
        #pragma unroll
        for (int nt = 0; nt < 8; nt++) {
            int r = m0 + mt * 16 + g;
            int n = warp_n * 64 + nt * 8 + c * 2;
            *reinterpret_cast<float2*>(out + (size_t)r * DOUT + n) =
                make_float2(acc[mt][nt][0], acc[mt][nt][1]);
            *reinterpret_cast<float2*>(out + (size_t)(r + 8) * DOUT + n) =
                make_float2(acc[mt][nt][2], acc[mt][nt][3]);
        }
    }
}

// ---------------- launch ----------------
extern "C" void kernel_launch(void* const* d_in, const int* in_sizes, int n_in,
                              void* d_out, int out_size) {
    const float* X = (const float*)d_in[0];
    const float* A = (const float*)d_in[1];
    const float* W = (const float*)d_in[2];
    const float* b = (const float*)d_in[3];
    float* out = (float*)d_out;

    cudaFuncSetAttribute(gemm1_kernel, cudaFuncAttributeMaxDynamicSharedMemorySize, SMEM1);
    cudaFuncSetAttribute(gemm2_kernel, cudaFuncAttributeMaxDynamicSharedMemorySize, SMEM2);

    void* wt = nullptr;
    cudaGetSymbolAddress(&wt, g_WT4);

    pack_w_kernel<<<(DIN * DOUT + 255) / 256, 256>>>(W);
    gemm1_kernel<<<128, 256, SMEM1>>>(X, (const __half*)wt, b);
    gemm2_kernel<<<128, 384, SMEM2>>>(A, out);
}